// round 7
// baseline (speedup 1.0000x reference)
#include <cuda_runtime.h>

// ---------------------------------------------------------------------------
// Model_19095424598065 v7 : algebraically reduced graph-spectral net.
// vs v6: duplicated-PAIR memory layouts (XF, Um, Y stored as (v,v) pairs) so
// every f32x2 broadcast operand comes straight out of an LDS/LDG with zero
// MOV packing; M streamed as ulonglong2 (reg-pair = f32x2 operand).
// ---------------------------------------------------------------------------

typedef unsigned long long u64t;

#define NT 256
#define TT 8

__device__ float d_M0[8 * 128 * 128];
__device__ float d_M2[8 * 128 * 128];
__device__ float d_tv[8];
__device__ float d_b1[128];
__device__ float d_b3[128];
__device__ float d_bsum[2];

// ------------------------------ helpers ------------------------------------
static __device__ __forceinline__ u64t dup2(float x) {
    u64t r; asm("mov.b64 %0, {%1, %1};" : "=l"(r) : "f"(x)); return r;
}
static __device__ __forceinline__ u64t pack2(float a, float b) {
    u64t r; asm("mov.b64 %0, {%1, %2};" : "=l"(r) : "f"(a), "f"(b)); return r;
}
static __device__ __forceinline__ void unpack2(u64t v, float& a, float& b) {
    asm("mov.b64 {%0, %1}, %2;" : "=f"(a), "=f"(b) : "l"(v));
}
static __device__ __forceinline__ void fma2(u64t& d, u64t a, u64t b) {
    asm("fma.rn.f32x2 %0, %1, %2, %3;" : "=l"(d) : "l"(a), "l"(b), "l"(d));
}
static __device__ __forceinline__ u64t add2(u64t a, u64t b) {
    u64t r; asm("add.rn.f32x2 %0, %1, %2;" : "=l"(r) : "l"(a), "l"(b)); return r;
}

// --------------------------- fused precompute ------------------------------
__global__ void pre_kernel(const float* __restrict__ U, const float* __restrict__ adj,
                           const float* __restrict__ w0, const float* __restrict__ w2,
                           const float* __restrict__ Ws1, const float* __restrict__ Wn1,
                           const float* __restrict__ Ws3, const float* __restrict__ Wn3,
                           const float* __restrict__ bs1, const float* __restrict__ bn1,
                           const float* __restrict__ bs3, const float* __restrict__ bn3)
{
    __shared__ float sw[1024];
    __shared__ float spart[128];
    __shared__ float slam[8];
    const int b = blockIdx.x, c = threadIdx.x;
    const int which = b >> 7, i = b & 127;
    const float* w  = which ? w2  : w0;
    const float* Ws = which ? Ws3 : Ws1;
    const float* Wn = which ? Wn3 : Wn1;

    {
        const int k = c >> 4, s = c & 15;
        float part = 0.f;
        for (int n = s; n < 64; n += 16) {
            float g = 0.f;
            for (int m = 0; m < 64; m++) g += adj[n * 64 + m] * U[m * 64 + k];
            part += U[n * 64 + k] * g;
        }
        spart[c] = part;
    }
    for (int idx = c; idx < 1024; idx += 128) sw[idx] = w[i * 1024 + idx];
    __syncthreads();
    if (c < 8) {
        float lam = 0.f;
        for (int s = 0; s < 16; s++) lam += spart[c * 16 + s];
        slam[c] = lam;
    }
    if (b == 0) {
        if (c < 128) { d_b1[c] = bs1[c] + bn1[c]; d_b3[c] = bs3[c] + bn3[c]; }
        if (c < 8) {
            float ts = 0.f;
            for (int n = 0; n < 64; n++) ts += U[n * 64 + c];
            d_tv[c] = ts;
        }
        if (c == 0) {
            float s1 = 0.f, s3 = 0.f;
            for (int j = 0; j < 128; j++) {
                s1 += bs1[j] + bn1[j];
                s3 += bs3[j] + bn3[j];
            }
            d_bsum[0] = s1; d_bsum[1] = s3;
        }
    }
    __syncthreads();

    float lam[8], acc[8];
#pragma unroll
    for (int k = 0; k < 8; k++) { lam[k] = slam[k]; acc[k] = 0.f; }
#pragma unroll 2
    for (int j = 0; j < 128; j++) {
        float ws = __ldg(Ws + j * 128 + c);
        float wn = __ldg(Wn + j * 128 + c);
#pragma unroll
        for (int k = 0; k < 8; k++)
            acc[k] += sw[j * 8 + k] * fmaf(lam[k], wn, ws);
    }
    float* M = which ? d_M2 : d_M0;
#pragma unroll
    for (int k = 0; k < 8; k++) M[(k * 128 + i) * 128 + c] = acc[k];
}

// ------------------------------- main kernel -------------------------------
// smem (floats):
//  sFX  [0    ,16384)  rows (t,k) of 256 floats: XF in dup-pair layout
//                      (col j at 2j, duplicated); F output in first 128.
//  sUmD [16384,17408)  Um dup pairs: row n = 16 floats (u_k,u_k)...
//  sUmS [17408,17920)  Um scalar: row n = 8 floats
//  sWp  [17920,18944)  Wp[p][c]
//  sV   [18944,19968)  bp|b1|b3|g1|be1|g3|be3|bo(8)|tv(8)|bsum(2)
//  sYd  [19968,20992)  stage-A y dup pairs: row (t,k) = 16 floats
//  sWoB [20992,22016)  Wo pairs, per-lane swizzled (512 u64)
#define O_FX  0
#define O_UMD 16384
#define O_UMS 17408
#define O_WP  17920
#define O_V   18944
#define O_YD  19968
#define O_WOB 20992
#define SMEMF 22016

// F[t,k,:] = XF[t,k,:] @ M_k (K=128). Warp k owns mode k's rows.
// XF read as dup pairs (LDS.128 -> 2 broadcast operands); M as ulonglong2.
static __device__ __forceinline__ void mode_gemm(const float* __restrict__ M,
                                                 float* sFX, int tid)
{
    const int k = tid >> 5, lane = tid & 31;
    const ulonglong2* Mk2 = (const ulonglong2*)(M + k * 16384);
    u64t a01[TT], a23[TT];
#pragma unroll
    for (int t = 0; t < TT; t++) { a01[t] = 0ull; a23[t] = 0ull; }

    ulonglong2 m0 = __ldg(&Mk2[0 * 32 + lane]);
    ulonglong2 m1 = __ldg(&Mk2[1 * 32 + lane]);
    ulonglong2 m2 = __ldg(&Mk2[2 * 32 + lane]);
    ulonglong2 m3 = __ldg(&Mk2[3 * 32 + lane]);

    const float* rbase = sFX + k * 256;

#pragma unroll 1
    for (int i4 = 0; i4 < 32; i4++) {
        const int nx = (i4 + 1) & 31;  // wrap: final prefetch is an L1 hit
        ulonglong2 n0 = __ldg(&Mk2[(4 * nx + 0) * 32 + lane]);
        ulonglong2 n1 = __ldg(&Mk2[(4 * nx + 1) * 32 + lane]);
        ulonglong2 n2 = __ldg(&Mk2[(4 * nx + 2) * 32 + lane]);
        ulonglong2 n3 = __ldg(&Mk2[(4 * nx + 3) * 32 + lane]);

        const float* bp = rbase + 8 * i4;
#pragma unroll
        for (int t = 0; t < TT; t++) {
            // dup pairs for K = 4*i4 .. 4*i4+3  (uniform addr -> broadcast)
            ulonglong2 xA = *(const ulonglong2*)(bp + t * 2048);
            ulonglong2 xB = *(const ulonglong2*)(bp + t * 2048 + 4);
            fma2(a01[t], xA.x, m0.x); fma2(a23[t], xA.x, m0.y);
            fma2(a01[t], xA.y, m1.x); fma2(a23[t], xA.y, m1.y);
            fma2(a01[t], xB.x, m2.x); fma2(a23[t], xB.x, m2.y);
            fma2(a01[t], xB.y, m3.x); fma2(a23[t], xB.y, m3.y);
        }
        m0 = n0; m1 = n1; m2 = n2; m3 = n3;
    }
#pragma unroll
    for (int t = 0; t < TT; t++) {
        ulonglong2 fv; fv.x = a01[t]; fv.y = a23[t];
        *(ulonglong2*)(sFX + (t * 8 + k) * 256 + 4 * lane) = fv;
    }
}

// Fsum[k] = sum_c F[k,c]
static __device__ __forceinline__ void tile_fsum(const u64t* Fr0, const u64t* Fr1,
                                                 float* fsum)
{
#pragma unroll
    for (int k = 0; k < 8; k++) {
        u64t p = add2(Fr0[k], Fr1[k]);
        float a, b; unpack2(p, a, b);
        fsum[k] = a + b;
    }
#pragma unroll
    for (int m = 1; m < 32; m <<= 1) {
#pragma unroll
        for (int k = 0; k < 8; k++)
            fsum[k] += __shfl_xor_sync(0xffffffffu, fsum[k], m);
    }
}

// Stage C, warp = tile t: o = Um@F + b1 -> LN -> relu -> xf2 = Um^T h,
// written back into sFX rows (t,k) in dup-pair layout.
static __device__ __forceinline__ void tile_stageC(float* sFX, const float* sUmD,
                                                   const float* sUmS,
                                                   const float* sV, int t, int lane)
{
    u64t Fr0[8], Fr1[8];
#pragma unroll
    for (int k = 0; k < 8; k++) {
        ulonglong2 fv = *(const ulonglong2*)(sFX + (t * 8 + k) * 256 + 4 * lane);
        Fr0[k] = fv.x; Fr1[k] = fv.y;
    }
    const ulonglong2 bv = *(const ulonglong2*)(sV + 128 + 4 * lane);
    const u64t b01 = bv.x, b23 = bv.y;
    const float4 gq = *(const float4*)(sV + 384 + 4 * lane);
    const float4 eq = *(const float4*)(sV + 512 + 4 * lane);
    const float bsum = sV[920];

    float fsum[8];
    tile_fsum(Fr0, Fr1, fsum);

    u64t X20[8], X21[8];
#pragma unroll
    for (int k = 0; k < 8; k++) { X20[k] = 0ull; X21[k] = 0ull; }

#pragma unroll 4
    for (int n = 0; n < 64; n++) {
        // dup pairs of Um row n (uniform -> broadcast)
        ulonglong2 uA = *(const ulonglong2*)(sUmD + n * 16);
        ulonglong2 uB = *(const ulonglong2*)(sUmD + n * 16 + 4);
        ulonglong2 uC = *(const ulonglong2*)(sUmD + n * 16 + 8);
        ulonglong2 uD = *(const ulonglong2*)(sUmD + n * 16 + 12);
        u64t o0 = b01, o1 = b23;
        fma2(o0, uA.x, Fr0[0]); fma2(o1, uA.x, Fr1[0]);
        fma2(o0, uA.y, Fr0[1]); fma2(o1, uA.y, Fr1[1]);
        fma2(o0, uB.x, Fr0[2]); fma2(o1, uB.x, Fr1[2]);
        fma2(o0, uB.y, Fr0[3]); fma2(o1, uB.y, Fr1[3]);
        fma2(o0, uC.x, Fr0[4]); fma2(o1, uC.x, Fr1[4]);
        fma2(o0, uC.y, Fr0[5]); fma2(o1, uC.y, Fr1[5]);
        fma2(o0, uD.x, Fr0[6]); fma2(o1, uD.x, Fr1[6]);
        fma2(o0, uD.y, Fr0[7]); fma2(o1, uD.y, Fr1[7]);
        float a, b, c, d;
        unpack2(o0, a, b); unpack2(o1, c, d);
        // mean: linear in F (exact), scalar Um copy
        const float4 u0 = *(const float4*)(sUmS + n * 8);
        const float4 u1 = *(const float4*)(sUmS + n * 8 + 4);
        float s = bsum;
        s = fmaf(u0.x, fsum[0], s); s = fmaf(u0.y, fsum[1], s);
        s = fmaf(u0.z, fsum[2], s); s = fmaf(u0.w, fsum[3], s);
        s = fmaf(u1.x, fsum[4], s); s = fmaf(u1.y, fsum[5], s);
        s = fmaf(u1.z, fsum[6], s); s = fmaf(u1.w, fsum[7], s);
        float s2 = a * a + b * b + c * c + d * d;
#pragma unroll
        for (int m = 1; m < 32; m <<= 1)
            s2 += __shfl_xor_sync(0xffffffffu, s2, m);
        const float mu = s * 0.0078125f;
        const float rstd = rsqrtf(s2 * 0.0078125f - mu * mu + 1e-5f);
        u64t hA = pack2(fmaxf((a - mu) * rstd * gq.x + eq.x, 0.f),
                        fmaxf((b - mu) * rstd * gq.y + eq.y, 0.f));
        u64t hB = pack2(fmaxf((c - mu) * rstd * gq.z + eq.z, 0.f),
                        fmaxf((d - mu) * rstd * gq.w + eq.w, 0.f));
        fma2(X20[0], uA.x, hA); fma2(X21[0], uA.x, hB);
        fma2(X20[1], uA.y, hA); fma2(X21[1], uA.y, hB);
        fma2(X20[2], uB.x, hA); fma2(X21[2], uB.x, hB);
        fma2(X20[3], uB.y, hA); fma2(X21[3], uB.y, hB);
        fma2(X20[4], uC.x, hA); fma2(X21[4], uC.x, hB);
        fma2(X20[5], uC.y, hA); fma2(X21[5], uC.y, hB);
        fma2(X20[6], uD.x, hA); fma2(X21[6], uD.x, hB);
        fma2(X20[7], uD.y, hA); fma2(X21[7], uD.y, hB);
    }
    // write xf2 back in dup-pair layout (cols 4*lane..4*lane+3)
#pragma unroll
    for (int k = 0; k < 8; k++) {
        float a, b, c, d;
        unpack2(X20[k], a, b); unpack2(X21[k], c, d);
        float* dst = sFX + (t * 8 + k) * 256 + 8 * lane;
        *(float4*)(dst)     = make_float4(a, a, b, b);
        *(float4*)(dst + 4) = make_float4(c, c, d, d);
    }
}

// Stage E, warp = tile t: o = Um@F + b3 -> LN -> relu -> out = h@Wo + bo.
static __device__ __forceinline__ void tile_stageE(const float* sFX, const float* sUmD,
                                                   const float* sUmS,
                                                   const float* sV, const u64t* sWoB,
                                                   float* __restrict__ outg,
                                                   int t, int lane)
{
    u64t Fr0[8], Fr1[8];
#pragma unroll
    for (int k = 0; k < 8; k++) {
        ulonglong2 fv = *(const ulonglong2*)(sFX + (t * 8 + k) * 256 + 4 * lane);
        Fr0[k] = fv.x; Fr1[k] = fv.y;
    }
    const ulonglong2 bv = *(const ulonglong2*)(sV + 256 + 4 * lane);
    const u64t b01 = bv.x, b23 = bv.y;
    const float4 gq = *(const float4*)(sV + 640 + 4 * lane);
    const float4 eq = *(const float4*)(sV + 768 + 4 * lane);
    const float bsum = sV[921];

    float fsum[8];
    tile_fsum(Fr0, Fr1, fsum);

    // Wo registers: w2[j][q] = (Wo[4l+j][2q], Wo[4l+j][2q+1]); swizzled load
    u64t w2[4][4];
    {
        const int l7 = lane & 7;
#pragma unroll
        for (int u = 0; u < 8; u++) {
            int p = lane * 8 + (u ^ l7);
            u64t A = sWoB[2 * p], B = sWoB[2 * p + 1];
            const int j = u >> 1, qb = (u & 1) * 2;
            w2[j][qb] = A; w2[j][qb + 1] = B;
        }
    }
    const int g = lane >> 3;
    float2 boP = *(const float2*)(sV + 896 + 2 * g);

#pragma unroll 2
    for (int n = 0; n < 64; n++) {
        ulonglong2 uA = *(const ulonglong2*)(sUmD + n * 16);
        ulonglong2 uB = *(const ulonglong2*)(sUmD + n * 16 + 4);
        ulonglong2 uC = *(const ulonglong2*)(sUmD + n * 16 + 8);
        ulonglong2 uD = *(const ulonglong2*)(sUmD + n * 16 + 12);
        u64t o0 = b01, o1 = b23;
        fma2(o0, uA.x, Fr0[0]); fma2(o1, uA.x, Fr1[0]);
        fma2(o0, uA.y, Fr0[1]); fma2(o1, uA.y, Fr1[1]);
        fma2(o0, uB.x, Fr0[2]); fma2(o1, uB.x, Fr1[2]);
        fma2(o0, uB.y, Fr0[3]); fma2(o1, uB.y, Fr1[3]);
        fma2(o0, uC.x, Fr0[4]); fma2(o1, uC.x, Fr1[4]);
        fma2(o0, uC.y, Fr0[5]); fma2(o1, uC.y, Fr1[5]);
        fma2(o0, uD.x, Fr0[6]); fma2(o1, uD.x, Fr1[6]);
        fma2(o0, uD.y, Fr0[7]); fma2(o1, uD.y, Fr1[7]);
        float a, b, c, d;
        unpack2(o0, a, b); unpack2(o1, c, d);
        const float4 u0 = *(const float4*)(sUmS + n * 8);
        const float4 u1 = *(const float4*)(sUmS + n * 8 + 4);
        float s = bsum;
        s = fmaf(u0.x, fsum[0], s); s = fmaf(u0.y, fsum[1], s);
        s = fmaf(u0.z, fsum[2], s); s = fmaf(u0.w, fsum[3], s);
        s = fmaf(u1.x, fsum[4], s); s = fmaf(u1.y, fsum[5], s);
        s = fmaf(u1.z, fsum[6], s); s = fmaf(u1.w, fsum[7], s);
        float s2 = a * a + b * b + c * c + d * d;
#pragma unroll
        for (int m = 1; m < 32; m <<= 1)
            s2 += __shfl_xor_sync(0xffffffffu, s2, m);
        const float mu = s * 0.0078125f;
        const float rstd = rsqrtf(s2 * 0.0078125f - mu * mu + 1e-5f);
        float h0 = fmaxf((a - mu) * rstd * gq.x + eq.x, 0.f);
        float h1 = fmaxf((b - mu) * rstd * gq.y + eq.y, 0.f);
        float h2 = fmaxf((c - mu) * rstd * gq.z + eq.z, 0.f);
        float h3 = fmaxf((d - mu) * rstd * gq.w + eq.w, 0.f);

        u64t acc2[4] = {0ull, 0ull, 0ull, 0ull};
        u64t hb;
        hb = dup2(h0);
#pragma unroll
        for (int q = 0; q < 4; q++) fma2(acc2[q], hb, w2[0][q]);
        hb = dup2(h1);
#pragma unroll
        for (int q = 0; q < 4; q++) fma2(acc2[q], hb, w2[1][q]);
        hb = dup2(h2);
#pragma unroll
        for (int q = 0; q < 4; q++) fma2(acc2[q], hb, w2[2][q]);
        hb = dup2(h3);
#pragma unroll
        for (int q = 0; q < 4; q++) fma2(acc2[q], hb, w2[3][q]);

#pragma unroll
        for (int q = 0; q < 4; q++)
            acc2[q] = add2(acc2[q], __shfl_xor_sync(0xffffffffu, acc2[q], 16));
#pragma unroll
        for (int q = 0; q < 4; q++)
            acc2[q] = add2(acc2[q], __shfl_xor_sync(0xffffffffu, acc2[q], 8));
        u64t v = (g == 0) ? acc2[0] : (g == 1) ? acc2[1] : (g == 2) ? acc2[2] : acc2[3];
        v = add2(v, __shfl_xor_sync(0xffffffffu, v, 4));
        v = add2(v, __shfl_xor_sync(0xffffffffu, v, 2));
        v = add2(v, __shfl_xor_sync(0xffffffffu, v, 1));
        if ((lane & 7) == (n & 7)) {
            float x, y; unpack2(v, x, y);
            *(float2*)(outg + n * 8 + 2 * g) = make_float2(x + boP.x, y + boP.y);
        }
    }
}

__global__ void __launch_bounds__(NT, 2)
main_kernel(const float* __restrict__ x, const float* __restrict__ U,
            const float* __restrict__ Wp, const float* __restrict__ bp,
            const float* __restrict__ g1, const float* __restrict__ be1,
            const float* __restrict__ g3, const float* __restrict__ be3,
            const float* __restrict__ Wo, const float* __restrict__ bo,
            float* __restrict__ out)
{
    extern __shared__ float sm[];
    float* sFX  = sm + O_FX;
    float* sUmD = sm + O_UMD;
    float* sUmS = sm + O_UMS;
    float* sWp  = sm + O_WP;
    float* sV   = sm + O_V;
    float* sYd  = sm + O_YD;
    u64t*  sWoB = (u64t*)(sm + O_WOB);

    const int tid = threadIdx.x;
    const int wid = tid >> 5, lane = tid & 31;

    // ---- init ----
    if (tid < 64) {
#pragma unroll
        for (int k = 0; k < 8; k++) {
            float v = U[tid * 64 + k];
            sUmS[tid * 8 + k] = v;
            sUmD[tid * 16 + 2 * k]     = v;
            sUmD[tid * 16 + 2 * k + 1] = v;
        }
    }
    for (int i = tid; i < 1024; i += NT) sWp[i] = Wp[i];
    if (tid < 128) {
        sV[tid]       = bp[tid];
        sV[128 + tid] = d_b1[tid];
        sV[256 + tid] = d_b3[tid];
        sV[384 + tid] = g1[tid];
        sV[512 + tid] = be1[tid];
        sV[640 + tid] = g3[tid];
        sV[768 + tid] = be3[tid];
    }
    if (tid < 8) { sV[896 + tid] = bo[tid]; sV[904 + tid] = d_tv[tid]; }
    if (tid < 2) sV[920 + tid] = d_bsum[tid];
    if (tid < 256) {
        const int l = tid >> 3, u = (tid & 7) ^ (l & 7);
        const int j = u >> 1, qb = (u & 1) * 2;
        const int c = 4 * l + j;
        sWoB[2 * tid]     = pack2(Wo[c * 8 + 2 * qb],     Wo[c * 8 + 2 * qb + 1]);
        sWoB[2 * tid + 1] = pack2(Wo[c * 8 + 2 * qb + 2], Wo[c * 8 + 2 * qb + 3]);
    }
    __syncthreads();

    // ---- stage A pass 1: y[t][k][p] = sum_n Um[n,k] x[t][n][p] (dup output) ----
    {
        const int k = lane >> 2, q = lane & 3;
        const float2* xg2 = (const float2*)(x + (size_t)blockIdx.x * 4096 + wid * 512);
        u64t acc = 0ull;
#pragma unroll 4
        for (int n = 0; n < 64; n++) {
            u64t umP = *(const u64t*)(sUmD + n * 16 + 2 * k);  // dup pair
            float2 xv = __ldg(&xg2[n * 4 + q]);
            fma2(acc, umP, pack2(xv.x, xv.y));
        }
        float a, b; unpack2(acc, a, b);
        *(float4*)(sYd + (wid * 8 + k) * 16 + 4 * q) = make_float4(a, a, b, b);
    }
    __syncthreads();

    // ---- stage A pass 2: XF[t][k][c] dup = tv[k]*bp[c] + sum_p y Wp[p][c] ----
    // warp k writes rows (t,k) -> consumed by the same warp in mode_gemm.
    {
        const int k = wid, c4 = lane;
        const u64t tb = dup2(sV[904 + k]);
        const ulonglong2 bpv = *(const ulonglong2*)(sV + 4 * c4);
        ulonglong2 wpv[8];
#pragma unroll
        for (int p = 0; p < 8; p++)
            wpv[p] = *(const ulonglong2*)(sWp + p * 128 + 4 * c4);
#pragma unroll
        for (int t = 0; t < TT; t++) {
            u64t a01 = 0ull, a23 = 0ull;
            fma2(a01, tb, bpv.x);
            fma2(a23, tb, bpv.y);
#pragma unroll
            for (int p = 0; p < 8; p++) {
                u64t yb = *(const u64t*)(sYd + (t * 8 + k) * 16 + 2 * p);  // dup
                fma2(a01, yb, wpv[p].x);
                fma2(a23, yb, wpv[p].y);
            }
            float a, b, c, d;
            unpack2(a01, a, b); unpack2(a23, c, d);
            float* dst = sFX + (t * 8 + k) * 256 + 8 * c4;
            *(float4*)(dst)     = make_float4(a, a, b, b);
            *(float4*)(dst + 4) = make_float4(c, c, d, d);
        }
    }

    // ---- stage B ----
    mode_gemm(d_M0, sFX, tid);
    __syncthreads();

    // ---- stage C ----
    tile_stageC(sFX, sUmD, sUmS, sV, wid, lane);
    __syncthreads();

    // ---- stage D ----
    mode_gemm(d_M2, sFX, tid);
    __syncthreads();

    // ---- stage E ----
    float* outg = out + (size_t)blockIdx.x * 4096;
    tile_stageE(sFX, sUmD, sUmS, sV, sWoB, outg + wid * 512, wid, lane);
}

// ------------------------------- launch ------------------------------------

extern "C" void kernel_launch(void* const* d_in, const int* in_sizes, int n_in,
                              void* d_out, int out_size)
{
    const float* x   = (const float*)d_in[0];
    const float* adj = (const float*)d_in[1];
    const float* U   = (const float*)d_in[2];
    const float* Wp  = (const float*)d_in[3];
    const float* bp  = (const float*)d_in[4];
    const float* w0  = (const float*)d_in[5];
    const float* w2  = (const float*)d_in[6];
    const float* Ws1 = (const float*)d_in[7];
    const float* bs1 = (const float*)d_in[8];
    const float* Wn1 = (const float*)d_in[9];
    const float* bn1 = (const float*)d_in[10];
    const float* g1  = (const float*)d_in[11];
    const float* be1 = (const float*)d_in[12];
    const float* Ws3 = (const float*)d_in[13];
    const float* bs3 = (const float*)d_in[14];
    const float* Wn3 = (const float*)d_in[15];
    const float* bn3 = (const float*)d_in[16];
    const float* g3  = (const float*)d_in[17];
    const float* be3 = (const float*)d_in[18];
    const float* Wo  = (const float*)d_in[19];
    const float* bo  = (const float*)d_in[20];
    float* out = (float*)d_out;

    pre_kernel<<<256, 128>>>(U, adj, w0, w2, Ws1, Wn1, Ws3, Wn3,
                             bs1, bn1, bs3, bn3);

    const size_t smem = SMEMF * sizeof(float);  // 86 KB -> 2 CTAs/SM
    cudaFuncSetAttribute(main_kernel, cudaFuncAttributeMaxDynamicSharedMemorySize,
                         (int)smem);
    main_kernel<<<2048, NT, smem>>>(x, U, Wp, bp, g1, be1, g3, be3, Wo, bo, out);
}

// round 8
// speedup vs baseline: 1.1817x; 1.1817x over previous
#include <cuda_runtime.h>

// ---------------------------------------------------------------------------
// Model_19095424598065 v8 : algebraically reduced graph-spectral net.
// = v4 main kernel (best measured: 544us, fma 55%) + v6 fused single
// precompute kernel (~90us launch/precompute overhead removed) + 2-way ILP
// split of the per-node o-accumulation chain in stages C/E.
// ---------------------------------------------------------------------------

typedef unsigned long long u64t;

#define NT 256
#define TT 8

__device__ float d_M0[8 * 128 * 128];
__device__ float d_M2[8 * 128 * 128];
__device__ float d_tv[8];
__device__ float d_b1[128];
__device__ float d_b3[128];

// ------------------------------ helpers ------------------------------------
static __device__ __forceinline__ u64t dup2(float x) {
    u64t r; asm("mov.b64 %0, {%1, %1};" : "=l"(r) : "f"(x)); return r;
}
static __device__ __forceinline__ u64t pack2(float a, float b) {
    u64t r; asm("mov.b64 %0, {%1, %2};" : "=l"(r) : "f"(a), "f"(b)); return r;
}
static __device__ __forceinline__ void unpack2(u64t v, float& a, float& b) {
    asm("mov.b64 {%0, %1}, %2;" : "=f"(a), "=f"(b) : "l"(v));
}
static __device__ __forceinline__ void fma2(u64t& d, u64t a, u64t b) {
    asm("fma.rn.f32x2 %0, %1, %2, %3;" : "=l"(d) : "l"(a), "l"(b), "l"(d));
}
static __device__ __forceinline__ u64t add2(u64t a, u64t b) {
    u64t r; asm("add.rn.f32x2 %0, %1, %2;" : "=l"(r) : "l"(a), "l"(b)); return r;
}

// --------------------------- fused precompute ------------------------------
// 256 blocks: block b<128 -> M0 row b; b>=128 -> M2 row b-128.
// Each block computes lam locally. Block 0 also fills d_tv/d_b1/d_b3.
__global__ void pre_kernel(const float* __restrict__ U, const float* __restrict__ adj,
                           const float* __restrict__ w0, const float* __restrict__ w2,
                           const float* __restrict__ Ws1, const float* __restrict__ Wn1,
                           const float* __restrict__ Ws3, const float* __restrict__ Wn3,
                           const float* __restrict__ bs1, const float* __restrict__ bn1,
                           const float* __restrict__ bs3, const float* __restrict__ bn3)
{
    __shared__ float sw[1024];
    __shared__ float spart[128];
    __shared__ float slam[8];
    const int b = blockIdx.x, c = threadIdx.x;
    const int which = b >> 7, i = b & 127;
    const float* w  = which ? w2  : w0;
    const float* Ws = which ? Ws3 : Ws1;
    const float* Wn = which ? Wn3 : Wn1;

    // lam[k] = u_k^T adj u_k, 16 threads per k
    {
        const int k = c >> 4, s = c & 15;
        float part = 0.f;
        for (int n = s; n < 64; n += 16) {
            float g = 0.f;
            for (int m = 0; m < 64; m++) g += adj[n * 64 + m] * U[m * 64 + k];
            part += U[n * 64 + k] * g;
        }
        spart[c] = part;
    }
    for (int idx = c; idx < 1024; idx += 128) sw[idx] = w[i * 1024 + idx];
    __syncthreads();
    if (c < 8) {
        float lam = 0.f;
        for (int s = 0; s < 16; s++) lam += spart[c * 16 + s];
        slam[c] = lam;
    }
    if (b == 0) {
        if (c < 128) { d_b1[c] = bs1[c] + bn1[c]; d_b3[c] = bs3[c] + bn3[c]; }
        if (c < 8) {
            float ts = 0.f;
            for (int n = 0; n < 64; n++) ts += U[n * 64 + c];
            d_tv[c] = ts;
        }
    }
    __syncthreads();

    float lam[8], acc[8];
#pragma unroll
    for (int k = 0; k < 8; k++) { lam[k] = slam[k]; acc[k] = 0.f; }
#pragma unroll 2
    for (int j = 0; j < 128; j++) {
        float ws = __ldg(Ws + j * 128 + c);
        float wn = __ldg(Wn + j * 128 + c);
#pragma unroll
        for (int k = 0; k < 8; k++)
            acc[k] += sw[j * 8 + k] * fmaf(lam[k], wn, ws);
    }
    float* M = which ? d_M2 : d_M0;
#pragma unroll
    for (int k = 0; k < 8; k++) M[(k * 128 + i) * 128 + c] = acc[k];
}

// ------------------------------- main kernel -------------------------------
// smem (floats):
//  sFX  [0    , 8192 )  XF/F in place [t][k][c]
//  sUm  [8192 , 8704 )  Um[n][k] stride 8
//  sWp  [8704 , 9728 )  Wp[p][c]
//  sV   [9728 , 10752)  bp|b1|b3|g1|be1|g3|be3|bo(8)|tv(8)
//  sY   [10752, 11264)  stage-A y[t][k][p]
//  sWoB [11264, 12288)  Wo pairs, per-lane swizzled (512 u64)
#define O_FX  0
#define O_UM  8192
#define O_WP  8704
#define O_V   9728
#define O_Y   10752
#define O_WOB 11264
#define SMEMF 12288

// F[t,k,:] = XF[t,k,:] @ M_k (K=128), in place. Warp k owns mode k's rows.
static __device__ __forceinline__ void mode_gemm(const float* __restrict__ M,
                                                 float* sFX, int tid)
{
    const int k = tid >> 5, lane = tid & 31;
    const float4* Mk4 = (const float4*)(M + k * 16384);
    u64t a01[TT], a23[TT];
#pragma unroll
    for (int t = 0; t < TT; t++) { a01[t] = 0ull; a23[t] = 0ull; }

#pragma unroll 2
    for (int i4 = 0; i4 < 32; i4++) {
        float4 xv[TT];
#pragma unroll
        for (int t = 0; t < TT; t++)  // uniform address -> broadcast, 1 wf
            xv[t] = *(const float4*)(sFX + (t * 8 + k) * 128 + 4 * i4);
#pragma unroll
        for (int ii = 0; ii < 4; ii++) {
            float4 m = __ldg(&Mk4[(4 * i4 + ii) * 32 + lane]);
            u64t m01 = pack2(m.x, m.y), m23 = pack2(m.z, m.w);
#pragma unroll
            for (int t = 0; t < TT; t++) {
                float xs = (ii == 0) ? xv[t].x : (ii == 1) ? xv[t].y
                         : (ii == 2) ? xv[t].z : xv[t].w;
                u64t xb = dup2(xs);
                fma2(a01[t], xb, m01);
                fma2(a23[t], xb, m23);
            }
        }
    }
#pragma unroll
    for (int t = 0; t < TT; t++) {
        float a, b, c, d;
        unpack2(a01[t], a, b); unpack2(a23[t], c, d);
        *(float4*)(sFX + (t * 8 + k) * 128 + 4 * lane) = make_float4(a, b, c, d);
    }
}

// Stage C, one warp = one tile t: o = Um@F + b1 -> LN -> relu -> xf2 = Um^T h,
// xf2 accumulated in registers, written back into sFX rows (t,k).
// o-accumulation split into two 4-deep chains for ILP.
static __device__ __forceinline__ void tile_stageC(float* sFX, const float* sUm,
                                                   const float* sV, int t, int lane)
{
    u64t Fr0[8], Fr1[8];
#pragma unroll
    for (int k = 0; k < 8; k++) {
        float4 f = *(const float4*)(sFX + (t * 8 + k) * 128 + 4 * lane);
        Fr0[k] = pack2(f.x, f.y); Fr1[k] = pack2(f.z, f.w);
    }
    const float4 bq = *(const float4*)(sV + 128 + 4 * lane);
    const float4 gq = *(const float4*)(sV + 384 + 4 * lane);
    const float4 eq = *(const float4*)(sV + 512 + 4 * lane);
    const u64t b01 = pack2(bq.x, bq.y), b23 = pack2(bq.z, bq.w);

    u64t X20[8], X21[8];
#pragma unroll
    for (int k = 0; k < 8; k++) { X20[k] = 0ull; X21[k] = 0ull; }

#pragma unroll 4
    for (int n = 0; n < 64; n++) {
        float4 u0 = *(const float4*)(sUm + n * 8);      // uniform -> broadcast
        float4 u1 = *(const float4*)(sUm + n * 8 + 4);
        u64t uk[8] = {dup2(u0.x), dup2(u0.y), dup2(u0.z), dup2(u0.w),
                      dup2(u1.x), dup2(u1.y), dup2(u1.z), dup2(u1.w)};
        u64t o0a = b01, o1a = b23, o0b = 0ull, o1b = 0ull;
#pragma unroll
        for (int k = 0; k < 4; k++) { fma2(o0a, uk[k], Fr0[k]); fma2(o1a, uk[k], Fr1[k]); }
#pragma unroll
        for (int k = 4; k < 8; k++) { fma2(o0b, uk[k], Fr0[k]); fma2(o1b, uk[k], Fr1[k]); }
        u64t o0 = add2(o0a, o0b), o1 = add2(o1a, o1b);
        float a, b, c, d;
        unpack2(o0, a, b); unpack2(o1, c, d);
        float s = a + b + c + d;
        float s2 = a * a + b * b + c * c + d * d;
#pragma unroll
        for (int m = 1; m < 32; m <<= 1) {
            s  += __shfl_xor_sync(0xffffffffu, s, m);
            s2 += __shfl_xor_sync(0xffffffffu, s2, m);
        }
        const float mu = s * 0.0078125f;
        const float rstd = rsqrtf(s2 * 0.0078125f - mu * mu + 1e-5f);
        u64t hA = pack2(fmaxf((a - mu) * rstd * gq.x + eq.x, 0.f),
                        fmaxf((b - mu) * rstd * gq.y + eq.y, 0.f));
        u64t hB = pack2(fmaxf((c - mu) * rstd * gq.z + eq.z, 0.f),
                        fmaxf((d - mu) * rstd * gq.w + eq.w, 0.f));
#pragma unroll
        for (int k = 0; k < 8; k++) { fma2(X20[k], uk[k], hA); fma2(X21[k], uk[k], hB); }
    }
#pragma unroll
    for (int k = 0; k < 8; k++) {
        float a, b, c, d;
        unpack2(X20[k], a, b); unpack2(X21[k], c, d);
        *(float4*)(sFX + (t * 8 + k) * 128 + 4 * lane) = make_float4(a, b, c, d);
    }
}

// Stage E, one warp = one tile: o = Um@F + b3 -> LN -> relu -> out = h@Wo + bo.
// Wo held in per-lane registers (swizzled smem load); butterfly reductions;
// 2-lane predicated STG per node. o-chain ILP split as in stage C.
static __device__ __forceinline__ void tile_stageE(const float* sFX, const float* sUm,
                                                   const float* sV, const u64t* sWoB,
                                                   float* __restrict__ outg,
                                                   int t, int lane)
{
    u64t Fr0[8], Fr1[8];
#pragma unroll
    for (int k = 0; k < 8; k++) {
        float4 f = *(const float4*)(sFX + (t * 8 + k) * 128 + 4 * lane);
        Fr0[k] = pack2(f.x, f.y); Fr1[k] = pack2(f.z, f.w);
    }
    const float4 bq = *(const float4*)(sV + 256 + 4 * lane);
    const float4 gq = *(const float4*)(sV + 640 + 4 * lane);
    const float4 eq = *(const float4*)(sV + 768 + 4 * lane);
    const u64t b01 = pack2(bq.x, bq.y), b23 = pack2(bq.z, bq.w);

    // Wo registers: w2[j][q] = (Wo[4l+j][2q], Wo[4l+j][2q+1]); swizzled load
    u64t w2[4][4];
    {
        const int l7 = lane & 7;
#pragma unroll
        for (int u = 0; u < 8; u++) {
            int p = lane * 8 + (u ^ l7);
            u64t A = sWoB[2 * p], B = sWoB[2 * p + 1];
            const int j = u >> 1, qb = (u & 1) * 2;
            w2[j][qb] = A; w2[j][qb + 1] = B;
        }
    }
    const int g = lane >> 3;
    float2 boP = *(const float2*)(sV + 896 + 2 * g);

#pragma unroll 2
    for (int n = 0; n < 64; n++) {
        float4 u0 = *(const float4*)(sUm + n * 8);
        float4 u1 = *(const float4*)(sUm + n * 8 + 4);
        u64t uk[8] = {dup2(u0.x), dup2(u0.y), dup2(u0.z), dup2(u0.w),
                      dup2(u1.x), dup2(u1.y), dup2(u1.z), dup2(u1.w)};
        u64t o0a = b01, o1a = b23, o0b = 0ull, o1b = 0ull;
#pragma unroll
        for (int k = 0; k < 4; k++) { fma2(o0a, uk[k], Fr0[k]); fma2(o1a, uk[k], Fr1[k]); }
#pragma unroll
        for (int k = 4; k < 8; k++) { fma2(o0b, uk[k], Fr0[k]); fma2(o1b, uk[k], Fr1[k]); }
        u64t o0 = add2(o0a, o0b), o1 = add2(o1a, o1b);
        float a, b, c, d;
        unpack2(o0, a, b); unpack2(o1, c, d);
        float s = a + b + c + d;
        float s2 = a * a + b * b + c * c + d * d;
#pragma unroll
        for (int m = 1; m < 32; m <<= 1) {
            s  += __shfl_xor_sync(0xffffffffu, s, m);
            s2 += __shfl_xor_sync(0xffffffffu, s2, m);
        }
        const float mu = s * 0.0078125f;
        const float rstd = rsqrtf(s2 * 0.0078125f - mu * mu + 1e-5f);
        float h0 = fmaxf((a - mu) * rstd * gq.x + eq.x, 0.f);
        float h1 = fmaxf((b - mu) * rstd * gq.y + eq.y, 0.f);
        float h2 = fmaxf((c - mu) * rstd * gq.z + eq.z, 0.f);
        float h3 = fmaxf((d - mu) * rstd * gq.w + eq.w, 0.f);

        u64t acc2[4] = {0ull, 0ull, 0ull, 0ull};
        u64t hb;
        hb = dup2(h0);
#pragma unroll
        for (int q = 0; q < 4; q++) fma2(acc2[q], hb, w2[0][q]);
        hb = dup2(h1);
#pragma unroll
        for (int q = 0; q < 4; q++) fma2(acc2[q], hb, w2[1][q]);
        hb = dup2(h2);
#pragma unroll
        for (int q = 0; q < 4; q++) fma2(acc2[q], hb, w2[2][q]);
        hb = dup2(h3);
#pragma unroll
        for (int q = 0; q < 4; q++) fma2(acc2[q], hb, w2[3][q]);

        // full butterfly over c-groups 16, 8
#pragma unroll
        for (int q = 0; q < 4; q++)
            acc2[q] = add2(acc2[q], __shfl_xor_sync(0xffffffffu, acc2[q], 16));
#pragma unroll
        for (int q = 0; q < 4; q++)
            acc2[q] = add2(acc2[q], __shfl_xor_sync(0xffffffffu, acc2[q], 8));
        // each 8-lane group keeps its own output pair
        u64t v = (g == 0) ? acc2[0] : (g == 1) ? acc2[1] : (g == 2) ? acc2[2] : acc2[3];
        v = add2(v, __shfl_xor_sync(0xffffffffu, v, 4));
        v = add2(v, __shfl_xor_sync(0xffffffffu, v, 2));
        v = add2(v, __shfl_xor_sync(0xffffffffu, v, 1));
        if ((lane & 7) == (n & 7)) {
            float x, y; unpack2(v, x, y);
            *(float2*)(outg + n * 8 + 2 * g) = make_float2(x + boP.x, y + boP.y);
        }
    }
}

__global__ void __launch_bounds__(NT, 2)
main_kernel(const float* __restrict__ x, const float* __restrict__ U,
            const float* __restrict__ Wp, const float* __restrict__ bp,
            const float* __restrict__ g1, const float* __restrict__ be1,
            const float* __restrict__ g3, const float* __restrict__ be3,
            const float* __restrict__ Wo, const float* __restrict__ bo,
            float* __restrict__ out)
{
    extern __shared__ float sm[];
    float* sFX  = sm + O_FX;
    float* sUm  = sm + O_UM;
    float* sWp  = sm + O_WP;
    float* sV   = sm + O_V;
    float* sY   = sm + O_Y;
    u64t*  sWoB = (u64t*)(sm + O_WOB);

    const int tid = threadIdx.x;
    const int wid = tid >> 5, lane = tid & 31;

    // ---- init: weights/vectors ----
    if (tid < 64) {
#pragma unroll
        for (int k = 0; k < 8; k++) sUm[tid * 8 + k] = U[tid * 64 + k];
    }
    for (int i = tid; i < 1024; i += NT) sWp[i] = Wp[i];
    if (tid < 128) {
        sV[tid]       = bp[tid];
        sV[128 + tid] = d_b1[tid];
        sV[256 + tid] = d_b3[tid];
        sV[384 + tid] = g1[tid];
        sV[512 + tid] = be1[tid];
        sV[640 + tid] = g3[tid];
        sV[768 + tid] = be3[tid];
    }
    if (tid < 8) { sV[896 + tid] = bo[tid]; sV[904 + tid] = d_tv[tid]; }
    // Wo pairs, swizzled: physical unit p=tid<256 -> (l=p>>3, u=(p&7)^(l&7))
    if (tid < 256) {
        const int l = tid >> 3, u = (tid & 7) ^ (l & 7);
        const int j = u >> 1, qb = (u & 1) * 2;
        const int c = 4 * l + j;
        sWoB[2 * tid]     = pack2(Wo[c * 8 + 2 * qb],     Wo[c * 8 + 2 * qb + 1]);
        sWoB[2 * tid + 1] = pack2(Wo[c * 8 + 2 * qb + 2], Wo[c * 8 + 2 * qb + 3]);
    }
    __syncthreads();

    // ---- stage A pass 1: y[t][k][p] = sum_n Um[n,k] x[t][n][p] ----
    {
        const int k = lane >> 2, q = lane & 3;
        const float2* xg2 = (const float2*)(x + (size_t)blockIdx.x * 4096 + wid * 512);
        u64t acc = 0ull;
#pragma unroll 4
        for (int n = 0; n < 64; n++) {
            float um = sUm[n * 8 + k];
            float2 xv = __ldg(&xg2[n * 4 + q]);
            fma2(acc, dup2(um), pack2(xv.x, xv.y));
        }
        float a, b; unpack2(acc, a, b);
        *(float2*)(sY + wid * 64 + k * 8 + 2 * q) = make_float2(a, b);
    }
    __syncthreads();

    // ---- stage A pass 2: XF[t][k][c] = tv[k]*bp[c] + sum_p y[t][k][p] Wp[p][c] ----
    // warp k writes rows (t,k) -> consumed by the same warp in mode_gemm (no sync)
    {
        const int k = wid, c4 = lane;
        const float tvk = sV[904 + k];
        const float4 bp4 = ((const float4*)sV)[c4];
#pragma unroll
        for (int t = 0; t < TT; t++) {
            const float* yv = sY + t * 64 + k * 8;
            u64t a01 = 0ull, a23 = 0ull;
            u64t tb = dup2(tvk);
            fma2(a01, tb, pack2(bp4.x, bp4.y));
            fma2(a23, tb, pack2(bp4.z, bp4.w));
#pragma unroll
            for (int p = 0; p < 8; p++) {
                u64t yb = dup2(yv[p]);
                float4 wp = ((const float4*)(sWp + p * 128))[c4];
                fma2(a01, yb, pack2(wp.x, wp.y));
                fma2(a23, yb, pack2(wp.z, wp.w));
            }
            float a, b, c, d;
            unpack2(a01, a, b); unpack2(a23, c, d);
            *(float4*)(sFX + (t * 8 + k) * 128 + 4 * c4) = make_float4(a, b, c, d);
        }
    }

    // ---- stage B: f0 = per-mode GEMM with M0 (in place) ----
    mode_gemm(d_M0, sFX, tid);
    __syncthreads();

    // ---- stage C: warp w handles tile w entirely ----
    tile_stageC(sFX, sUm, sV, wid, lane);
    __syncthreads();

    // ---- stage D: f2 = per-mode GEMM with M2 (in place) ----
    mode_gemm(d_M2, sFX, tid);
    __syncthreads();

    // ---- stage E: warp w handles tile w entirely, fused output projection ----
    float* outg = out + (size_t)blockIdx.x * 4096;
    tile_stageE(sFX, sUm, sV, sWoB, outg + wid * 512, wid, lane);
}

// ------------------------------- launch ------------------------------------

extern "C" void kernel_launch(void* const* d_in, const int* in_sizes, int n_in,
                              void* d_out, int out_size)
{
    const float* x   = (const float*)d_in[0];
    const float* adj = (const float*)d_in[1];
    const float* U   = (const float*)d_in[2];
    const float* Wp  = (const float*)d_in[3];
    const float* bp  = (const float*)d_in[4];
    const float* w0  = (const float*)d_in[5];
    const float* w2  = (const float*)d_in[6];
    const float* Ws1 = (const float*)d_in[7];
    const float* bs1 = (const float*)d_in[8];
    const float* Wn1 = (const float*)d_in[9];
    const float* bn1 = (const float*)d_in[10];
    const float* g1  = (const float*)d_in[11];
    const float* be1 = (const float*)d_in[12];
    const float* Ws3 = (const float*)d_in[13];
    const float* bs3 = (const float*)d_in[14];
    const float* Wn3 = (const float*)d_in[15];
    const float* bn3 = (const float*)d_in[16];
    const float* g3  = (const float*)d_in[17];
    const float* be3 = (const float*)d_in[18];
    const float* Wo  = (const float*)d_in[19];
    const float* bo  = (const float*)d_in[20];
    float* out = (float*)d_out;

    pre_kernel<<<256, 128>>>(U, adj, w0, w2, Ws1, Wn1, Ws3, Wn3,
                             bs1, bn1, bs3, bn3);

    const size_t smem = SMEMF * sizeof(float);  // 48 KB -> 2 CTAs/SM
    cudaFuncSetAttribute(main_kernel, cudaFuncAttributeMaxDynamicSharedMemorySize,
                         (int)smem);
    main_kernel<<<2048, NT, smem>>>(x, U, Wp, bp, g1, be1, g3, be3, Wo, bo, out);
}